// round 15
// baseline (speedup 1.0000x reference)
#include <cuda_runtime.h>
#include <math.h>
#include <stdint.h>

#define NB 16
#define NPT 4096
#define MTOT (NB*NPT)   // 65536 points

__device__ __forceinline__ float gelu_f(float x) {
    // exact tanh-approx GELU, tanh computed via exp (matches tanhf to ~1e-6)
    float u = 0.7978845608028654f * (x + 0.044715f * x * x * x);
    float a = fabsf(u);
    float e = __expf(-2.0f * a);
    float t = __fdividef(1.0f - e, 1.0f + e);
    return 0.5f * x * (1.0f + copysignf(t, u));
}

__device__ __forceinline__ uint32_t f2tf32(float x) {
    uint32_t u;
    asm("cvt.rna.tf32.f32 %0, %1;" : "=r"(u) : "f"(x));
    return u;
}

// ---------------- scratch buffers ----------------
__device__ float g_c1[NB*16*112*112];
__device__ float g_c2[NB*32*56*56];
__device__ float g_fmap[NB*4*56*56];
__device__ float g_ga[NB*4*112*112];
__device__ float g_gb[NB*8*56*56];
__device__ float g_gcs[NB*16*28*28];
__device__ float g_gd[NB*32*14*14];
__device__ float g_ge[NB*64*7*7];
__device__ float g_gvec[NB*64];
__device__ float g_gcon[NB*512];
__device__ float g_Wcat[512*512];
__device__ float g_biasC[512];
__device__ float g_embed[MTOT*48];
__device__ float g_feat[(size_t)MTOT*512];

// ---------------- templated 3x3 conv, pad 1, smem weights, gelu ----------------
template<int CIN, int STRIDE>
__global__ void conv3x3_gelu_t(const float* __restrict__ in, const float* __restrict__ w,
                               const float* __restrict__ bias, float* __restrict__ out,
                               int Hin, int Win, int Hout, int Wout) {
    __shared__ float sw[CIN * 9];
    __shared__ float sb;
    const int co = blockIdx.y;
    const int b = blockIdx.z;
    const int Cout = gridDim.y;
    for (int i = threadIdx.x; i < CIN * 9; i += blockDim.x) sw[i] = w[co * CIN * 9 + i];
    if (threadIdx.x == 0) sb = bias[co];
    __syncthreads();
    int p = blockIdx.x * blockDim.x + threadIdx.x;
    if (p >= Hout * Wout) return;
    int oy = p / Wout, ox = p % Wout;
    const float* ip = in + (size_t)b * CIN * Hin * Win;
    int iy0 = oy * STRIDE - 1, ix0 = ox * STRIDE - 1;
    float acc = sb;
    if (iy0 >= 0 && ix0 >= 0 && iy0 + 2 < Hin && ix0 + 2 < Win) {
        #pragma unroll
        for (int ci = 0; ci < CIN; ci++) {
            const float* base = ip + (size_t)ci * Hin * Win + iy0 * Win + ix0;
            const float* wp = sw + ci * 9;
            #pragma unroll
            for (int ky = 0; ky < 3; ky++)
                #pragma unroll
                for (int kx = 0; kx < 3; kx++)
                    acc += base[ky * Win + kx] * wp[ky * 3 + kx];
        }
    } else {
        #pragma unroll
        for (int ci = 0; ci < CIN; ci++) {
            const float* basec = ip + (size_t)ci * Hin * Win;
            const float* wp = sw + ci * 9;
            #pragma unroll
            for (int ky = 0; ky < 3; ky++) {
                int iy = iy0 + ky;
                #pragma unroll
                for (int kx = 0; kx < 3; kx++) {
                    int ix = ix0 + kx;
                    if (iy >= 0 && iy < Hin && ix >= 0 && ix < Win)
                        acc += basec[iy * Win + ix] * wp[ky * 3 + kx];
                }
            }
        }
    }
    out[((size_t)(b * Cout + co)) * Hout * Wout + p] = gelu_f(acc);
}

// ---------------- global pooling ----------------
__global__ void gpool_kernel() {
    int idx = blockIdx.x * blockDim.x + threadIdx.x;
    if (idx >= NB * 64) return;
    const float* p = g_ge + idx * 49;
    float s = 0.f;
    #pragma unroll
    for (int i = 0; i < 49; i++) s += p[i];
    g_gvec[idx] = s * (1.0f / 49.0f);
}

// ---------------- per-batch gc contribution ----------------
__global__ void gcon_kernel(const float* __restrict__ hw1) {
    int idx = blockIdx.x * blockDim.x + threadIdx.x;
    if (idx >= NB * 512) return;
    int b = idx >> 9, j = idx & 511;
    float acc = 0.f;
    const float* gv = g_gvec + b * 64;
    const float* hp = hw1 + j * 576 + 512;
    #pragma unroll
    for (int c = 0; c < 64; c++) acc += gv[c] * hp[c];
    g_gcon[idx] = acc;
}

// ---------------- head weight prep ----------------
__global__ void prep_head(const float* __restrict__ hw1, const float* __restrict__ hb1,
                          const float* __restrict__ lw2, const float* __restrict__ lb2) {
    int j = blockIdx.x;
    int t = threadIdx.x;
    const float* hrow = hw1 + j * 576;
    float acc = 0.f;
    for (int c = 0; c < 256; c++)
        acc += hrow[c] * lw2[c * 256 + t];
    g_Wcat[j * 512 + t] = acc;
    g_Wcat[j * 512 + 256 + t] = hrow[256 + t];
    __shared__ float s[256];
    s[t] = hrow[t] * lb2[t];
    __syncthreads();
    for (int o = 128; o > 0; o >>= 1) {
        if (t < o) s[t] += s[t + o];
        __syncthreads();
    }
    if (t == 0) g_biasC[j] = hb1[j] + s[0];
}

// ---------------- positional embedding ----------------
__global__ void embed_kernel(const float* __restrict__ points) {
    int idx = blockIdx.x * blockDim.x + threadIdx.x;
    if (idx >= MTOT * 12) return;
    int m = idx / 12, i = idx % 12;
    float f = (float)(1 << i);
    float px = points[m * 2 + 0], py = points[m * 2 + 1];
    float sx, cx, sy, cy;
    sincosf(f * px, &sx, &cx);
    sincosf(f * py, &sy, &cy);
    float* e = g_embed + m * 48 + 4 * i;
    e[0] = sx; e[1] = sy; e[2] = cx; e[3] = cy;
}

// ---------------- bilinear patch gather ----------------
__global__ void patch_kernel(const float* __restrict__ points) {
    int idx = blockIdx.x * blockDim.x + threadIdx.x;
    if (idx >= MTOT * 64) return;
    int pp = idx & 63;
    int m = idx >> 6;
    int i = pp >> 3, j = pp & 7;
    int b = m >> 12;
    float px = points[m * 2 + 0], py = points[m * 2 + 1];
    const float step = 2.0f / 55.0f;
    float gx = (px * 2.0f - 1.0f) + ((float)i - 3.5f) * step;
    float gy = (py * 2.0f - 1.0f) + ((float)j - 3.5f) * step;
    float ix = (gx + 1.0f) * 0.5f * 55.0f;
    float iy = (gy + 1.0f) * 0.5f * 55.0f;
    float x0f = floorf(ix), y0f = floorf(iy);
    int x0 = (int)x0f, y0 = (int)y0f;
    int x1 = x0 + 1, y1 = y0 + 1;
    float wx1 = ix - x0f, wx0 = 1.0f - wx1;
    float wy1 = iy - y0f, wy0 = 1.0f - wy1;
    bool vx0 = (x0 >= 0) & (x0 < 56), vx1 = (x1 >= 0) & (x1 < 56);
    bool vy0 = (y0 >= 0) & (y0 < 56), vy1 = (y1 >= 0) & (y1 < 56);
    int cx0 = min(max(x0, 0), 55), cx1 = min(max(x1, 0), 55);
    int cy0 = min(max(y0, 0), 55), cy1 = min(max(y1, 0), 55);
    float w00 = wx0 * wy0 * ((vx0 && vy0) ? 1.f : 0.f);
    float w10 = wx1 * wy0 * ((vx1 && vy0) ? 1.f : 0.f);
    float w01 = wx0 * wy1 * ((vx0 && vy1) ? 1.f : 0.f);
    float w11 = wx1 * wy1 * ((vx1 && vy1) ? 1.f : 0.f);
    int i00 = cy0 * 56 + cx0, i10 = cy0 * 56 + cx1;
    int i01 = cy1 * 56 + cx0, i11 = cy1 * 56 + cx1;
    const float* fm = g_fmap + (size_t)b * 4 * 3136;
    float* fo = g_feat + (size_t)m * 512 + 256 + pp;
    #pragma unroll
    for (int c = 0; c < 4; c++) {
        const float* base = fm + c * 3136;
        float v = w00 * base[i00] + w10 * base[i10] + w01 * base[i01] + w11 * base[i11];
        fo[c * 64] = v;
    }
}

// ---------------- out init ----------------
__global__ void init_out(float* __restrict__ out, const float* __restrict__ hb2) {
    int i = blockIdx.x * blockDim.x + threadIdx.x;
    if (i < MTOT) out[i] = hb2[0];
}

// =====================================================================================
// TF32 tensor-core GEMM, 128x128 tile, K-chunk KC, double-buffered smem,
// pair-packed (k, k+4) fragments -> 64-bit LDS fragment loads.
//   FUSED=true : out[m] += sum_j gelu(acc + bias[j] + gcon[b,j]) * hw2[j]  (atomicAdd)
//   FUSED=false: C[m,j] = gelu(acc + bias[j])                              (C = out, ldc)
// =====================================================================================
#define SMS 132   // padded row stride (uint2 units)

template<int K, int KC, bool FUSED>
__global__ __launch_bounds__(256) void gemm_tf32(
    const float* __restrict__ A, const float* __restrict__ W,
    const float* __restrict__ bias, const float* __restrict__ gcon,
    const float* __restrict__ hw2, float* __restrict__ out, int ldc) {

    constexpr int PS = KC / 2;                 // pair slots per chunk
    constexpr int NKT = K / KC;                // K chunks
    constexpr int NR = (128 * KC / 4) / 256;   // float4 loads per operand per thread
    constexpr int C4W = KC / 4;                // float4 per row per chunk
    constexpr int BUF = 2 * PS * SMS;          // uint2 per buffer (A+B)

    extern __shared__ uint2 sm[];

    const int tid = threadIdx.x;
    const int lane = tid & 31;
    const int warpId = tid >> 5;
    const int warpM = warpId & 1;        // 0..1 (64 rows each)
    const int warpN = warpId >> 1;       // 0..3 (32 cols each)
    const int tg = lane & 3;
    const int gid = lane >> 2;
    const int blockM = blockIdx.y * 128;
    const int blockN = blockIdx.x * 128;

    int lrow[NR], lc4[NR];
    #pragma unroll
    for (int r = 0; r < NR; r++) {
        int lin = r * 256 + tid;
        lrow[r] = lin / C4W;
        lc4[r] = lin % C4W;
    }
    const float* Abase = A + (size_t)blockM * K;
    const float* Wbase = W + (size_t)blockN * K;

    float4 pa[NR], pb[NR];

    auto loadg = [&](int k0) {
        #pragma unroll
        for (int r = 0; r < NR; r++) {
            pa[r] = *reinterpret_cast<const float4*>(Abase + (size_t)lrow[r] * K + k0 + lc4[r] * 4);
            pb[r] = *reinterpret_cast<const float4*>(Wbase + (size_t)lrow[r] * K + k0 + lc4[r] * 4);
        }
    };
    auto storesm = [&](int buf) {
        uint2* As = sm + buf * BUF;
        uint2* Bs = As + PS * SMS;
        #pragma unroll
        for (int r = 0; r < NR; r++) {
            int sb0 = (lc4[r] >> 1) * 4;
            int comp = lc4[r] & 1;
            uint32_t* pA0 = reinterpret_cast<uint32_t*>(&As[(sb0 + 0) * SMS + lrow[r]]);
            uint32_t* pA1 = reinterpret_cast<uint32_t*>(&As[(sb0 + 1) * SMS + lrow[r]]);
            uint32_t* pA2 = reinterpret_cast<uint32_t*>(&As[(sb0 + 2) * SMS + lrow[r]]);
            uint32_t* pA3 = reinterpret_cast<uint32_t*>(&As[(sb0 + 3) * SMS + lrow[r]]);
            pA0[comp] = f2tf32(pa[r].x); pA1[comp] = f2tf32(pa[r].y);
            pA2[comp] = f2tf32(pa[r].z); pA3[comp] = f2tf32(pa[r].w);
            uint32_t* pB0 = reinterpret_cast<uint32_t*>(&Bs[(sb0 + 0) * SMS + lrow[r]]);
            uint32_t* pB1 = reinterpret_cast<uint32_t*>(&Bs[(sb0 + 1) * SMS + lrow[r]]);
            uint32_t* pB2 = reinterpret_cast<uint32_t*>(&Bs[(sb0 + 2) * SMS + lrow[r]]);
            uint32_t* pB3 = reinterpret_cast<uint32_t*>(&Bs[(sb0 + 3) * SMS + lrow[r]]);
            pB0[comp] = f2tf32(pb[r].x); pB1[comp] = f2tf32(pb[r].y);
            pB2[comp] = f2tf32(pb[r].z); pB3[comp] = f2tf32(pb[r].w);
        }
    };

    float acc[4][4][4];
    #pragma unroll
    for (int mi = 0; mi < 4; mi++)
        #pragma unroll
        for (int ni = 0; ni < 4; ni++)
            #pragma unroll
            for (int c = 0; c < 4; c++) acc[mi][ni][c] = 0.f;

    loadg(0);
    storesm(0);
    __syncthreads();

    const int rowB = warpM * 64;
    const int colB = warpN * 32;

    #pragma unroll 1
    for (int kt = 0; kt < NKT; kt++) {
        if (kt + 1 < NKT) loadg((kt + 1) * KC);
        const uint2* As = sm + (kt & 1) * BUF;
        const uint2* Bs = As + PS * SMS;
        #pragma unroll
        for (int kk = 0; kk < KC / 8; kk++) {
            const int sb0 = kk * 4 + tg;
            uint2 a0[4], a1[4];
            #pragma unroll
            for (int mi = 0; mi < 4; mi++) {
                int r0 = rowB + mi * 16 + gid;
                a0[mi] = As[sb0 * SMS + r0];
                a1[mi] = As[sb0 * SMS + r0 + 8];
            }
            uint2 bfr[4];
            #pragma unroll
            for (int ni = 0; ni < 4; ni++) {
                int c0 = colB + ni * 8 + gid;
                bfr[ni] = Bs[sb0 * SMS + c0];
            }
            #pragma unroll
            for (int mi = 0; mi < 4; mi++)
                #pragma unroll
                for (int ni = 0; ni < 4; ni++) {
                    asm volatile(
                        "mma.sync.aligned.m16n8k8.row.col.f32.tf32.tf32.f32 "
                        "{%0,%1,%2,%3}, {%4,%5,%6,%7}, {%8,%9}, {%0,%1,%2,%3};"
                        : "+f"(acc[mi][ni][0]), "+f"(acc[mi][ni][1]),
                          "+f"(acc[mi][ni][2]), "+f"(acc[mi][ni][3])
                        : "r"(a0[mi].x), "r"(a1[mi].x), "r"(a0[mi].y), "r"(a1[mi].y),
                          "r"(bfr[ni].x), "r"(bfr[ni].y));
                }
        }
        if (kt + 1 < NKT) {
            storesm((kt + 1) & 1);
            __syncthreads();
        }
    }

    if (FUSED) {
        const int batch = blockM >> 12;
        float addc[8], w2c[8];
        #pragma unroll
        for (int ni = 0; ni < 4; ni++) {
            int c0 = blockN + colB + ni * 8 + tg * 2;
            addc[ni * 2 + 0] = bias[c0] + gcon[batch * 512 + c0];
            addc[ni * 2 + 1] = bias[c0 + 1] + gcon[batch * 512 + c0 + 1];
            w2c[ni * 2 + 0] = hw2[c0];
            w2c[ni * 2 + 1] = hw2[c0 + 1];
        }
        #pragma unroll
        for (int mi = 0; mi < 4; mi++) {
            float s0 = 0.f, s1 = 0.f;
            #pragma unroll
            for (int ni = 0; ni < 4; ni++) {
                s0 += gelu_f(acc[mi][ni][0] + addc[ni * 2 + 0]) * w2c[ni * 2 + 0];
                s0 += gelu_f(acc[mi][ni][1] + addc[ni * 2 + 1]) * w2c[ni * 2 + 1];
                s1 += gelu_f(acc[mi][ni][2] + addc[ni * 2 + 0]) * w2c[ni * 2 + 0];
                s1 += gelu_f(acc[mi][ni][3] + addc[ni * 2 + 1]) * w2c[ni * 2 + 1];
            }
            s0 += __shfl_xor_sync(0xFFFFFFFFu, s0, 1);
            s0 += __shfl_xor_sync(0xFFFFFFFFu, s0, 2);
            s1 += __shfl_xor_sync(0xFFFFFFFFu, s1, 1);
            s1 += __shfl_xor_sync(0xFFFFFFFFu, s1, 2);
            if (tg == 0) {
                int r0 = blockM + rowB + mi * 16 + gid;
                atomicAdd(out + r0, s0);
                atomicAdd(out + r0 + 8, s1);
            }
        }
    } else {
        #pragma unroll
        for (int mi = 0; mi < 4; mi++) {
            int r0 = blockM + rowB + mi * 16 + gid;
            #pragma unroll
            for (int ni = 0; ni < 4; ni++) {
                int c0 = blockN + colB + ni * 8 + tg * 2;
                float b0 = bias[c0], b1 = bias[c0 + 1];
                float2 v0 = make_float2(gelu_f(acc[mi][ni][0] + b0), gelu_f(acc[mi][ni][1] + b1));
                float2 v1 = make_float2(gelu_f(acc[mi][ni][2] + b0), gelu_f(acc[mi][ni][3] + b1));
                *reinterpret_cast<float2*>(out + (size_t)r0 * ldc + c0) = v0;
                *reinterpret_cast<float2*>(out + (size_t)(r0 + 8) * ldc + c0) = v1;
            }
        }
    }
}

// =====================================================================================
extern "C" void kernel_launch(void* const* d_in, const int* in_sizes, int n_in,
                              void* d_out, int out_size) {
    const float* points = (const float*)d_in[0];
    const float* images = (const float*)d_in[1];
    const float* pw1 = (const float*)d_in[2];  const float* pb1 = (const float*)d_in[3];
    const float* pw2 = (const float*)d_in[4];  const float* pb2 = (const float*)d_in[5];
    const float* pw3 = (const float*)d_in[6];  const float* pb3 = (const float*)d_in[7];
    const float* gw1 = (const float*)d_in[8];  const float* gb1 = (const float*)d_in[9];
    const float* gw2 = (const float*)d_in[10]; const float* gb2 = (const float*)d_in[11];
    const float* gw3 = (const float*)d_in[12]; const float* gb3 = (const float*)d_in[13];
    const float* gw4 = (const float*)d_in[14]; const float* gb4 = (const float*)d_in[15];
    const float* gw5 = (const float*)d_in[16]; const float* gb5 = (const float*)d_in[17];
    const float* lw1 = (const float*)d_in[18]; const float* lb1 = (const float*)d_in[19];
    const float* lw2 = (const float*)d_in[20]; const float* lb2 = (const float*)d_in[21];
    const float* hw1 = (const float*)d_in[22]; const float* hb1 = (const float*)d_in[23];
    const float* hw2 = (const float*)d_in[24]; const float* hb2 = (const float*)d_in[25];
    float* out = (float*)d_out;

    float *c1, *c2, *fmap, *ga, *gb_, *gcs, *gd, *ge, *Wcat, *biasC, *emb, *feat, *gcon;
    cudaGetSymbolAddress((void**)&c1, g_c1);
    cudaGetSymbolAddress((void**)&c2, g_c2);
    cudaGetSymbolAddress((void**)&fmap, g_fmap);
    cudaGetSymbolAddress((void**)&ga, g_ga);
    cudaGetSymbolAddress((void**)&gb_, g_gb);
    cudaGetSymbolAddress((void**)&gcs, g_gcs);
    cudaGetSymbolAddress((void**)&gd, g_gd);
    cudaGetSymbolAddress((void**)&ge, g_ge);
    cudaGetSymbolAddress((void**)&Wcat, g_Wcat);
    cudaGetSymbolAddress((void**)&biasC, g_biasC);
    cudaGetSymbolAddress((void**)&emb, g_embed);
    cudaGetSymbolAddress((void**)&feat, g_feat);
    cudaGetSymbolAddress((void**)&gcon, g_gcon);

    const int T = 256;
    auto blocks = [](int n) { return (n + 255) / 256; };

    // dynamic smem sizes for the tf32 GEMMs
    const int smem2 = 2 * 2 * (32 / 2) * SMS * (int)sizeof(uint2);   // 67584 B
    const int smem1 = 2 * 2 * (16 / 2) * SMS * (int)sizeof(uint2);   // 33792 B
    cudaFuncSetAttribute(gemm_tf32<512, 32, true>,
                         cudaFuncAttributeMaxDynamicSharedMemorySize, smem2);
    cudaFuncSetAttribute(gemm_tf32<48, 16, false>,
                         cudaFuncAttributeMaxDynamicSharedMemorySize, smem1);

    // ----- plane encoder -----
    conv3x3_gelu_t<3, 2><<<dim3(49, 16, NB), T>>>(images, pw1, pb1, c1, 224, 224, 112, 112);
    conv3x3_gelu_t<16, 2><<<dim3(13, 32, NB), T>>>(c1, pw2, pb2, c2, 112, 112, 56, 56);
    conv3x3_gelu_t<32, 1><<<dim3(13, 4, NB), T>>>(c2, pw3, pb3, fmap, 56, 56, 56, 56);

    // ----- global encoder -----
    conv3x3_gelu_t<3, 2><<<dim3(49, 4, NB), T>>>(images, gw1, gb1, ga, 224, 224, 112, 112);
    conv3x3_gelu_t<4, 2><<<dim3(13, 8, NB), T>>>(ga, gw2, gb2, gb_, 112, 112, 56, 56);
    conv3x3_gelu_t<8, 2><<<dim3(4, 16, NB), T>>>(gb_, gw3, gb3, gcs, 56, 56, 28, 28);
    conv3x3_gelu_t<16, 2><<<dim3(1, 32, NB), T>>>(gcs, gw4, gb4, gd, 28, 28, 14, 14);
    conv3x3_gelu_t<32, 2><<<dim3(1, 64, NB), T>>>(gd, gw5, gb5, ge, 14, 14, 7, 7);
    gpool_kernel<<<blocks(NB*64), T>>>();

    // ----- fold weights / per-batch contributions -----
    prep_head<<<512, 256>>>(hw1, hb1, lw2, lb2);
    gcon_kernel<<<blocks(NB*512), T>>>(hw1);

    // ----- point branch: embed + tf32 GEMM1 into feat[:, 0:256] -----
    embed_kernel<<<blocks(MTOT*12), T>>>(points);
    {
        dim3 grid(256 / 128, MTOT / 128);
        gemm_tf32<48, 16, false><<<grid, 256, smem1>>>(emb, lw1, lb1, nullptr, nullptr, feat, 512);
    }

    // ----- patch gather into feat[:, 256:512] -----
    patch_kernel<<<blocks(MTOT*64), T>>>(points);

    // ----- head GEMM (tf32) fused with final reduction -----
    init_out<<<blocks(MTOT), T>>>(out, hb2);
    {
        dim3 grid(512 / 128, MTOT / 128);
        gemm_tf32<512, 32, true><<<grid, 256, smem2>>>(feat, Wcat, biasC, gcon, hw2, out, 0);
    }
}

// round 16
// speedup vs baseline: 1.0007x; 1.0007x over previous
#include <cuda_runtime.h>
#include <math.h>
#include <stdint.h>

#define NB 16
#define NPT 4096
#define MTOT (NB*NPT)   // 65536 points

__device__ __forceinline__ float gelu_f(float x) {
    // exact tanh-approx GELU, tanh computed via exp (matches tanhf to ~1e-6)
    float u = 0.7978845608028654f * (x + 0.044715f * x * x * x);
    float a = fabsf(u);
    float e = __expf(-2.0f * a);
    float t = __fdividef(1.0f - e, 1.0f + e);
    return 0.5f * x * (1.0f + copysignf(t, u));
}

__device__ __forceinline__ uint32_t f2tf32(float x) {
    uint32_t u;
    asm("cvt.rna.tf32.f32 %0, %1;" : "=r"(u) : "f"(x));
    return u;
}

// ---------------- scratch buffers ----------------
__device__ float g_c1[NB*16*112*112];
__device__ float g_c2[NB*32*56*56];
__device__ float g_fmap[NB*4*56*56];
__device__ float g_ga[NB*4*112*112];
__device__ float g_gb[NB*8*56*56];
__device__ float g_gcs[NB*16*28*28];
__device__ float g_gd[NB*32*14*14];
__device__ float g_ge[NB*64*7*7];
__device__ float g_gvec[NB*64];
__device__ float g_gcon[NB*512];
__device__ float g_Wcat[512*512];
__device__ float g_biasC[512];
__device__ float g_embed[MTOT*48];
__device__ float g_feat[(size_t)MTOT*512];

// ---------------- templated 3x3 conv, pad 1, smem weights, gelu ----------------
template<int CIN, int STRIDE>
__global__ void conv3x3_gelu_t(const float* __restrict__ in, const float* __restrict__ w,
                               const float* __restrict__ bias, float* __restrict__ out,
                               int Hin, int Win, int Hout, int Wout) {
    __shared__ float sw[CIN * 9];
    __shared__ float sb;
    const int co = blockIdx.y;
    const int b = blockIdx.z;
    const int Cout = gridDim.y;
    for (int i = threadIdx.x; i < CIN * 9; i += blockDim.x) sw[i] = w[co * CIN * 9 + i];
    if (threadIdx.x == 0) sb = bias[co];
    __syncthreads();
    int p = blockIdx.x * blockDim.x + threadIdx.x;
    if (p >= Hout * Wout) return;
    int oy = p / Wout, ox = p % Wout;
    const float* ip = in + (size_t)b * CIN * Hin * Win;
    int iy0 = oy * STRIDE - 1, ix0 = ox * STRIDE - 1;
    float acc = sb;
    if (iy0 >= 0 && ix0 >= 0 && iy0 + 2 < Hin && ix0 + 2 < Win) {
        #pragma unroll
        for (int ci = 0; ci < CIN; ci++) {
            const float* base = ip + (size_t)ci * Hin * Win + iy0 * Win + ix0;
            const float* wp = sw + ci * 9;
            #pragma unroll
            for (int ky = 0; ky < 3; ky++)
                #pragma unroll
                for (int kx = 0; kx < 3; kx++)
                    acc += base[ky * Win + kx] * wp[ky * 3 + kx];
        }
    } else {
        #pragma unroll
        for (int ci = 0; ci < CIN; ci++) {
            const float* basec = ip + (size_t)ci * Hin * Win;
            const float* wp = sw + ci * 9;
            #pragma unroll
            for (int ky = 0; ky < 3; ky++) {
                int iy = iy0 + ky;
                #pragma unroll
                for (int kx = 0; kx < 3; kx++) {
                    int ix = ix0 + kx;
                    if (iy >= 0 && iy < Hin && ix >= 0 && ix < Win)
                        acc += basec[iy * Win + ix] * wp[ky * 3 + kx];
                }
            }
        }
    }
    out[((size_t)(b * Cout + co)) * Hout * Wout + p] = gelu_f(acc);
}

// ---------------- global pooling ----------------
__global__ void gpool_kernel() {
    int idx = blockIdx.x * blockDim.x + threadIdx.x;
    if (idx >= NB * 64) return;
    const float* p = g_ge + idx * 49;
    float s = 0.f;
    #pragma unroll
    for (int i = 0; i < 49; i++) s += p[i];
    g_gvec[idx] = s * (1.0f / 49.0f);
}

// ---------------- per-batch gc contribution ----------------
__global__ void gcon_kernel(const float* __restrict__ hw1) {
    int idx = blockIdx.x * blockDim.x + threadIdx.x;
    if (idx >= NB * 512) return;
    int b = idx >> 9, j = idx & 511;
    float acc = 0.f;
    const float* gv = g_gvec + b * 64;
    const float* hp = hw1 + j * 576 + 512;
    #pragma unroll
    for (int c = 0; c < 64; c++) acc += gv[c] * hp[c];
    g_gcon[idx] = acc;
}

// ---------------- head weight prep ----------------
__global__ void prep_head(const float* __restrict__ hw1, const float* __restrict__ hb1,
                          const float* __restrict__ lw2, const float* __restrict__ lb2) {
    int j = blockIdx.x;
    int t = threadIdx.x;
    const float* hrow = hw1 + j * 576;
    float acc = 0.f;
    for (int c = 0; c < 256; c++)
        acc += hrow[c] * lw2[c * 256 + t];
    g_Wcat[j * 512 + t] = acc;
    g_Wcat[j * 512 + 256 + t] = hrow[256 + t];
    __shared__ float s[256];
    s[t] = hrow[t] * lb2[t];
    __syncthreads();
    for (int o = 128; o > 0; o >>= 1) {
        if (t < o) s[t] += s[t + o];
        __syncthreads();
    }
    if (t == 0) g_biasC[j] = hb1[j] + s[0];
}

// ---------------- positional embedding ----------------
__global__ void embed_kernel(const float* __restrict__ points) {
    int idx = blockIdx.x * blockDim.x + threadIdx.x;
    if (idx >= MTOT * 12) return;
    int m = idx / 12, i = idx % 12;
    float f = (float)(1 << i);
    float px = points[m * 2 + 0], py = points[m * 2 + 1];
    float sx, cx, sy, cy;
    sincosf(f * px, &sx, &cx);
    sincosf(f * py, &sy, &cy);
    float* e = g_embed + m * 48 + 4 * i;
    e[0] = sx; e[1] = sy; e[2] = cx; e[3] = cy;
}

// ---------------- bilinear patch gather ----------------
__global__ void patch_kernel(const float* __restrict__ points) {
    int idx = blockIdx.x * blockDim.x + threadIdx.x;
    if (idx >= MTOT * 64) return;
    int pp = idx & 63;
    int m = idx >> 6;
    int i = pp >> 3, j = pp & 7;
    int b = m >> 12;
    float px = points[m * 2 + 0], py = points[m * 2 + 1];
    const float step = 2.0f / 55.0f;
    float gx = (px * 2.0f - 1.0f) + ((float)i - 3.5f) * step;
    float gy = (py * 2.0f - 1.0f) + ((float)j - 3.5f) * step;
    float ix = (gx + 1.0f) * 0.5f * 55.0f;
    float iy = (gy + 1.0f) * 0.5f * 55.0f;
    float x0f = floorf(ix), y0f = floorf(iy);
    int x0 = (int)x0f, y0 = (int)y0f;
    int x1 = x0 + 1, y1 = y0 + 1;
    float wx1 = ix - x0f, wx0 = 1.0f - wx1;
    float wy1 = iy - y0f, wy0 = 1.0f - wy1;
    bool vx0 = (x0 >= 0) & (x0 < 56), vx1 = (x1 >= 0) & (x1 < 56);
    bool vy0 = (y0 >= 0) & (y0 < 56), vy1 = (y1 >= 0) & (y1 < 56);
    int cx0 = min(max(x0, 0), 55), cx1 = min(max(x1, 0), 55);
    int cy0 = min(max(y0, 0), 55), cy1 = min(max(y1, 0), 55);
    float w00 = wx0 * wy0 * ((vx0 && vy0) ? 1.f : 0.f);
    float w10 = wx1 * wy0 * ((vx1 && vy0) ? 1.f : 0.f);
    float w01 = wx0 * wy1 * ((vx0 && vy1) ? 1.f : 0.f);
    float w11 = wx1 * wy1 * ((vx1 && vy1) ? 1.f : 0.f);
    int i00 = cy0 * 56 + cx0, i10 = cy0 * 56 + cx1;
    int i01 = cy1 * 56 + cx0, i11 = cy1 * 56 + cx1;
    const float* fm = g_fmap + (size_t)b * 4 * 3136;
    float* fo = g_feat + (size_t)m * 512 + 256 + pp;
    #pragma unroll
    for (int c = 0; c < 4; c++) {
        const float* base = fm + c * 3136;
        float v = w00 * base[i00] + w10 * base[i10] + w01 * base[i01] + w11 * base[i11];
        fo[c * 64] = v;
    }
}

// ---------------- out init ----------------
__global__ void init_out(float* __restrict__ out, const float* __restrict__ hb2) {
    int i = blockIdx.x * blockDim.x + threadIdx.x;
    if (i < MTOT) out[i] = hb2[0];
}

// =====================================================================================
// TF32 tensor-core GEMM, 128x128 tile, K-chunk KC, double-buffered smem,
// pair-packed (k, k+4) fragments -> 64-bit LDS fragment loads.
//   FUSED=true : out[m] += sum_j gelu(acc + bias[j] + gcon[b,j]) * hw2[j]  (atomicAdd)
//   FUSED=false: C[m,j] = gelu(acc + bias[j])                              (C = out, ldc)
// =====================================================================================
#define SMS 132   // padded row stride (uint2 units)

template<int K, int KC, bool FUSED>
__global__ __launch_bounds__(256) void gemm_tf32(
    const float* __restrict__ A, const float* __restrict__ W,
    const float* __restrict__ bias, const float* __restrict__ gcon,
    const float* __restrict__ hw2, float* __restrict__ out, int ldc) {

    constexpr int PS = KC / 2;                 // pair slots per chunk
    constexpr int NKT = K / KC;                // K chunks
    constexpr int NR = (128 * KC / 4) / 256;   // float4 loads per operand per thread
    constexpr int C4W = KC / 4;                // float4 per row per chunk
    constexpr int BUF = 2 * PS * SMS;          // uint2 per buffer (A+B)

    extern __shared__ uint2 sm[];

    const int tid = threadIdx.x;
    const int lane = tid & 31;
    const int warpId = tid >> 5;
    const int warpM = warpId & 1;        // 0..1 (64 rows each)
    const int warpN = warpId >> 1;       // 0..3 (32 cols each)
    const int tg = lane & 3;
    const int gid = lane >> 2;
    const int blockM = blockIdx.y * 128;
    const int blockN = blockIdx.x * 128;

    int lrow[NR], lc4[NR];
    #pragma unroll
    for (int r = 0; r < NR; r++) {
        int lin = r * 256 + tid;
        lrow[r] = lin / C4W;
        lc4[r] = lin % C4W;
    }
    const float* Abase = A + (size_t)blockM * K;
    const float* Wbase = W + (size_t)blockN * K;

    float4 pa[NR], pb[NR];

    auto loadg = [&](int k0) {
        #pragma unroll
        for (int r = 0; r < NR; r++) {
            pa[r] = *reinterpret_cast<const float4*>(Abase + (size_t)lrow[r] * K + k0 + lc4[r] * 4);
            pb[r] = *reinterpret_cast<const float4*>(Wbase + (size_t)lrow[r] * K + k0 + lc4[r] * 4);
        }
    };
    auto storesm = [&](int buf) {
        uint2* As = sm + buf * BUF;
        uint2* Bs = As + PS * SMS;
        #pragma unroll
        for (int r = 0; r < NR; r++) {
            int sb0 = (lc4[r] >> 1) * 4;
            int comp = lc4[r] & 1;
            uint32_t* pA0 = reinterpret_cast<uint32_t*>(&As[(sb0 + 0) * SMS + lrow[r]]);
            uint32_t* pA1 = reinterpret_cast<uint32_t*>(&As[(sb0 + 1) * SMS + lrow[r]]);
            uint32_t* pA2 = reinterpret_cast<uint32_t*>(&As[(sb0 + 2) * SMS + lrow[r]]);
            uint32_t* pA3 = reinterpret_cast<uint32_t*>(&As[(sb0 + 3) * SMS + lrow[r]]);
            pA0[comp] = f2tf32(pa[r].x); pA1[comp] = f2tf32(pa[r].y);
            pA2[comp] = f2tf32(pa[r].z); pA3[comp] = f2tf32(pa[r].w);
            uint32_t* pB0 = reinterpret_cast<uint32_t*>(&Bs[(sb0 + 0) * SMS + lrow[r]]);
            uint32_t* pB1 = reinterpret_cast<uint32_t*>(&Bs[(sb0 + 1) * SMS + lrow[r]]);
            uint32_t* pB2 = reinterpret_cast<uint32_t*>(&Bs[(sb0 + 2) * SMS + lrow[r]]);
            uint32_t* pB3 = reinterpret_cast<uint32_t*>(&Bs[(sb0 + 3) * SMS + lrow[r]]);
            pB0[comp] = f2tf32(pb[r].x); pB1[comp] = f2tf32(pb[r].y);
            pB2[comp] = f2tf32(pb[r].z); pB3[comp] = f2tf32(pb[r].w);
        }
    };

    float acc[4][4][4];
    #pragma unroll
    for (int mi = 0; mi < 4; mi++)
        #pragma unroll
        for (int ni = 0; ni < 4; ni++)
            #pragma unroll
            for (int c = 0; c < 4; c++) acc[mi][ni][c] = 0.f;

    loadg(0);
    storesm(0);
    __syncthreads();

    const int rowB = warpM * 64;
    const int colB = warpN * 32;

    #pragma unroll 1
    for (int kt = 0; kt < NKT; kt++) {
        if (kt + 1 < NKT) loadg((kt + 1) * KC);
        const uint2* As = sm + (kt & 1) * BUF;
        const uint2* Bs = As + PS * SMS;
        #pragma unroll
        for (int kk = 0; kk < KC / 8; kk++) {
            const int sb0 = kk * 4 + tg;
            uint2 a0[4], a1[4];
            #pragma unroll
            for (int mi = 0; mi < 4; mi++) {
                int r0 = rowB + mi * 16 + gid;
                a0[mi] = As[sb0 * SMS + r0];
                a1[mi] = As[sb0 * SMS + r0 + 8];
            }
            uint2 bfr[4];
            #pragma unroll
            for (int ni = 0; ni < 4; ni++) {
                int c0 = colB + ni * 8 + gid;
                bfr[ni] = Bs[sb0 * SMS + c0];
            }
            #pragma unroll
            for (int mi = 0; mi < 4; mi++)
                #pragma unroll
                for (int ni = 0; ni < 4; ni++) {
                    asm volatile(
                        "mma.sync.aligned.m16n8k8.row.col.f32.tf32.tf32.f32 "
                        "{%0,%1,%2,%3}, {%4,%5,%6,%7}, {%8,%9}, {%0,%1,%2,%3};"
                        : "+f"(acc[mi][ni][0]), "+f"(acc[mi][ni][1]),
                          "+f"(acc[mi][ni][2]), "+f"(acc[mi][ni][3])
                        : "r"(a0[mi].x), "r"(a1[mi].x), "r"(a0[mi].y), "r"(a1[mi].y),
                          "r"(bfr[ni].x), "r"(bfr[ni].y));
                }
        }
        if (kt + 1 < NKT) {
            storesm((kt + 1) & 1);
            __syncthreads();
        }
    }

    if (FUSED) {
        const int batch = blockM >> 12;
        float addc[8], w2c[8];
        #pragma unroll
        for (int ni = 0; ni < 4; ni++) {
            int c0 = blockN + colB + ni * 8 + tg * 2;
            addc[ni * 2 + 0] = bias[c0] + gcon[batch * 512 + c0];
            addc[ni * 2 + 1] = bias[c0 + 1] + gcon[batch * 512 + c0 + 1];
            w2c[ni * 2 + 0] = hw2[c0];
            w2c[ni * 2 + 1] = hw2[c0 + 1];
        }
        #pragma unroll
        for (int mi = 0; mi < 4; mi++) {
            float s0 = 0.f, s1 = 0.f;
            #pragma unroll
            for (int ni = 0; ni < 4; ni++) {
                s0 += gelu_f(acc[mi][ni][0] + addc[ni * 2 + 0]) * w2c[ni * 2 + 0];
                s0 += gelu_f(acc[mi][ni][1] + addc[ni * 2 + 1]) * w2c[ni * 2 + 1];
                s1 += gelu_f(acc[mi][ni][2] + addc[ni * 2 + 0]) * w2c[ni * 2 + 0];
                s1 += gelu_f(acc[mi][ni][3] + addc[ni * 2 + 1]) * w2c[ni * 2 + 1];
            }
            s0 += __shfl_xor_sync(0xFFFFFFFFu, s0, 1);
            s0 += __shfl_xor_sync(0xFFFFFFFFu, s0, 2);
            s1 += __shfl_xor_sync(0xFFFFFFFFu, s1, 1);
            s1 += __shfl_xor_sync(0xFFFFFFFFu, s1, 2);
            if (tg == 0) {
                int r0 = blockM + rowB + mi * 16 + gid;
                atomicAdd(out + r0, s0);
                atomicAdd(out + r0 + 8, s1);
            }
        }
    } else {
        #pragma unroll
        for (int mi = 0; mi < 4; mi++) {
            int r0 = blockM + rowB + mi * 16 + gid;
            #pragma unroll
            for (int ni = 0; ni < 4; ni++) {
                int c0 = blockN + colB + ni * 8 + tg * 2;
                float b0 = bias[c0], b1 = bias[c0 + 1];
                float2 v0 = make_float2(gelu_f(acc[mi][ni][0] + b0), gelu_f(acc[mi][ni][1] + b1));
                float2 v1 = make_float2(gelu_f(acc[mi][ni][2] + b0), gelu_f(acc[mi][ni][3] + b1));
                *reinterpret_cast<float2*>(out + (size_t)r0 * ldc + c0) = v0;
                *reinterpret_cast<float2*>(out + (size_t)(r0 + 8) * ldc + c0) = v1;
            }
        }
    }
}

// =====================================================================================
extern "C" void kernel_launch(void* const* d_in, const int* in_sizes, int n_in,
                              void* d_out, int out_size) {
    const float* points = (const float*)d_in[0];
    const float* images = (const float*)d_in[1];
    const float* pw1 = (const float*)d_in[2];  const float* pb1 = (const float*)d_in[3];
    const float* pw2 = (const float*)d_in[4];  const float* pb2 = (const float*)d_in[5];
    const float* pw3 = (const float*)d_in[6];  const float* pb3 = (const float*)d_in[7];
    const float* gw1 = (const float*)d_in[8];  const float* gb1 = (const float*)d_in[9];
    const float* gw2 = (const float*)d_in[10]; const float* gb2 = (const float*)d_in[11];
    const float* gw3 = (const float*)d_in[12]; const float* gb3 = (const float*)d_in[13];
    const float* gw4 = (const float*)d_in[14]; const float* gb4 = (const float*)d_in[15];
    const float* gw5 = (const float*)d_in[16]; const float* gb5 = (const float*)d_in[17];
    const float* lw1 = (const float*)d_in[18]; const float* lb1 = (const float*)d_in[19];
    const float* lw2 = (const float*)d_in[20]; const float* lb2 = (const float*)d_in[21];
    const float* hw1 = (const float*)d_in[22]; const float* hb1 = (const float*)d_in[23];
    const float* hw2 = (const float*)d_in[24]; const float* hb2 = (const float*)d_in[25];
    float* out = (float*)d_out;

    float *c1, *c2, *fmap, *ga, *gb_, *gcs, *gd, *ge, *Wcat, *biasC, *emb, *feat, *gcon;
    cudaGetSymbolAddress((void**)&c1, g_c1);
    cudaGetSymbolAddress((void**)&c2, g_c2);
    cudaGetSymbolAddress((void**)&fmap, g_fmap);
    cudaGetSymbolAddress((void**)&ga, g_ga);
    cudaGetSymbolAddress((void**)&gb_, g_gb);
    cudaGetSymbolAddress((void**)&gcs, g_gcs);
    cudaGetSymbolAddress((void**)&gd, g_gd);
    cudaGetSymbolAddress((void**)&ge, g_ge);
    cudaGetSymbolAddress((void**)&Wcat, g_Wcat);
    cudaGetSymbolAddress((void**)&biasC, g_biasC);
    cudaGetSymbolAddress((void**)&emb, g_embed);
    cudaGetSymbolAddress((void**)&feat, g_feat);
    cudaGetSymbolAddress((void**)&gcon, g_gcon);

    const int T = 256;
    auto blocks = [](int n) { return (n + 255) / 256; };

    // dynamic smem sizes for the tf32 GEMMs
    const int smem2 = 2 * 2 * (32 / 2) * SMS * (int)sizeof(uint2);   // 67584 B
    const int smem1 = 2 * 2 * (16 / 2) * SMS * (int)sizeof(uint2);   // 33792 B
    cudaFuncSetAttribute(gemm_tf32<512, 32, true>,
                         cudaFuncAttributeMaxDynamicSharedMemorySize, smem2);
    cudaFuncSetAttribute(gemm_tf32<48, 16, false>,
                         cudaFuncAttributeMaxDynamicSharedMemorySize, smem1);

    // ----- plane encoder -----
    conv3x3_gelu_t<3, 2><<<dim3(49, 16, NB), T>>>(images, pw1, pb1, c1, 224, 224, 112, 112);
    conv3x3_gelu_t<16, 2><<<dim3(13, 32, NB), T>>>(c1, pw2, pb2, c2, 112, 112, 56, 56);
    conv3x3_gelu_t<32, 1><<<dim3(13, 4, NB), T>>>(c2, pw3, pb3, fmap, 56, 56, 56, 56);

    // ----- global encoder -----
    conv3x3_gelu_t<3, 2><<<dim3(49, 4, NB), T>>>(images, gw1, gb1, ga, 224, 224, 112, 112);
    conv3x3_gelu_t<4, 2><<<dim3(13, 8, NB), T>>>(ga, gw2, gb2, gb_, 112, 112, 56, 56);
    conv3x3_gelu_t<8, 2><<<dim3(4, 16, NB), T>>>(gb_, gw3, gb3, gcs, 56, 56, 28, 28);
    conv3x3_gelu_t<16, 2><<<dim3(1, 32, NB), T>>>(gcs, gw4, gb4, gd, 28, 28, 14, 14);
    conv3x3_gelu_t<32, 2><<<dim3(1, 64, NB), T>>>(gd, gw5, gb5, ge, 14, 14, 7, 7);
    gpool_kernel<<<blocks(NB*64), T>>>();

    // ----- fold weights / per-batch contributions -----
    prep_head<<<512, 256>>>(hw1, hb1, lw2, lb2);
    gcon_kernel<<<blocks(NB*512), T>>>(hw1);

    // ----- point branch: embed + tf32 GEMM1 into feat[:, 0:256] -----
    embed_kernel<<<blocks(MTOT*12), T>>>(points);
    {
        dim3 grid(256 / 128, MTOT / 128);
        gemm_tf32<48, 16, false><<<grid, 256, smem1>>>(emb, lw1, lb1, nullptr, nullptr, feat, 512);
    }

    // ----- patch gather into feat[:, 256:512] -----
    patch_kernel<<<blocks(MTOT*64), T>>>(points);

    // ----- head GEMM (tf32) fused with final reduction -----
    init_out<<<blocks(MTOT), T>>>(out, hb2);
    {
        dim3 grid(512 / 128, MTOT / 128);
        gemm_tf32<512, 32, true><<<grid, 256, smem2>>>(feat, Wcat, biasC, gcon, hw2, out, 0);
    }
}